// round 4
// baseline (speedup 1.0000x reference)
#include <cuda_runtime.h>
#include <math.h>
#include <float.h>

#define BB 8
#define EE 2048
#define DD 512
#define DA 64

typedef unsigned long long ull;

// Scratch (static __device__ arrays: allocation-guard safe)
__device__ float g_q[BB * EE * DD];
__device__ float g_k[BB * EE * DD];
__device__ float g_v[BB * EE * DD];
__device__ float g_s[(size_t)BB * EE * EE];

// ---------------------------------------------------------------------------
// packed f32x2 helpers
// ---------------------------------------------------------------------------
__device__ __forceinline__ ull pk2(float lo, float hi) {
    ull r;
    asm("mov.b64 %0, {%1,%2};" : "=l"(r) : "f"(lo), "f"(hi));
    return r;
}
__device__ __forceinline__ void ffma2(ull& c, ull a, ull b) {
    asm("fma.rn.f32x2 %0, %1, %2, %0;" : "+l"(c) : "l"(a), "l"(b));
}
__device__ __forceinline__ float2 upk2(ull v) {
    float2 f;
    asm("mov.b64 {%0,%1}, %2;" : "=f"(f.x), "=f"(f.y) : "l"(v));
    return f;
}

// ---------------------------------------------------------------------------
// 128x128 tile GEMM core, 8x8 per thread, f32x2 FMA, double-buffered smem.
// acc[rp][j]: rp = 4 row-pairs (rows packed in the f32x2 lanes), j = 8 cols.
//   rp0=(ty*4+0, ty*4+1) rp1=(ty*4+2, ty*4+3) rp2/rp3 = same +64.
//   j 0..3 -> col tx*4+j ; j 4..7 -> col 64+tx*4+(j-4)
// ---------------------------------------------------------------------------
template <bool BT>
__device__ __forceinline__ void mm_tile(
    const float* __restrict__ A, int lda,
    const float* __restrict__ B, int ldb,
    int Ktot, float (*As)[16][128], float (*Bs)[16][128], ull acc[4][8])
{
    const int t = threadIdx.x;
    const int a_c4 = (t & 3) << 2;   // k offset within chunk: 0,4,8,12
    const int a_r  = t >> 2;         // 0..63 (rows a_r and a_r+64)
    const int b_n4 = (t & 31) << 2;  // 0..124
    const int b_k  = t >> 5;         // 0..7
    const int tx = t & 15, ty = t >> 4;

    float4 ra0, ra1, rb0, rb1;

    // prologue: load k0 = 0
    ra0 = *(const float4*)(A + (size_t)a_r * lda + a_c4);
    ra1 = *(const float4*)(A + (size_t)(a_r + 64) * lda + a_c4);
    if (BT) {
        rb0 = *(const float4*)(B + (size_t)a_r * ldb + a_c4);
        rb1 = *(const float4*)(B + (size_t)(a_r + 64) * ldb + a_c4);
    } else {
        rb0 = *(const float4*)(B + (size_t)b_k * ldb + b_n4);
        rb1 = *(const float4*)(B + (size_t)(b_k + 8) * ldb + b_n4);
    }

    int buf = 0;
    // store prologue tile into buffer 0
    {
        As[0][a_c4 + 0][a_r] = ra0.x; As[0][a_c4 + 1][a_r] = ra0.y;
        As[0][a_c4 + 2][a_r] = ra0.z; As[0][a_c4 + 3][a_r] = ra0.w;
        As[0][a_c4 + 0][a_r + 64] = ra1.x; As[0][a_c4 + 1][a_r + 64] = ra1.y;
        As[0][a_c4 + 2][a_r + 64] = ra1.z; As[0][a_c4 + 3][a_r + 64] = ra1.w;
        if (BT) {
            Bs[0][a_c4 + 0][a_r] = rb0.x; Bs[0][a_c4 + 1][a_r] = rb0.y;
            Bs[0][a_c4 + 2][a_r] = rb0.z; Bs[0][a_c4 + 3][a_r] = rb0.w;
            Bs[0][a_c4 + 0][a_r + 64] = rb1.x; Bs[0][a_c4 + 1][a_r + 64] = rb1.y;
            Bs[0][a_c4 + 2][a_r + 64] = rb1.z; Bs[0][a_c4 + 3][a_r + 64] = rb1.w;
        } else {
            *(float4*)&Bs[0][b_k][b_n4] = rb0;
            *(float4*)&Bs[0][b_k + 8][b_n4] = rb1;
        }
    }
    __syncthreads();

    for (int k0 = 0; k0 < Ktot; k0 += 16) {
        const bool more = (k0 + 16) < Ktot;
        if (more) {
            int kn = k0 + 16;
            ra0 = *(const float4*)(A + (size_t)a_r * lda + kn + a_c4);
            ra1 = *(const float4*)(A + (size_t)(a_r + 64) * lda + kn + a_c4);
            if (BT) {
                rb0 = *(const float4*)(B + (size_t)a_r * ldb + kn + a_c4);
                rb1 = *(const float4*)(B + (size_t)(a_r + 64) * ldb + kn + a_c4);
            } else {
                rb0 = *(const float4*)(B + (size_t)(kn + b_k) * ldb + b_n4);
                rb1 = *(const float4*)(B + (size_t)(kn + b_k + 8) * ldb + b_n4);
            }
        }
#pragma unroll
        for (int kk = 0; kk < 16; kk++) {
            ulonglong2 ap0 = *(const ulonglong2*)&As[buf][kk][ty << 2];
            ulonglong2 ap1 = *(const ulonglong2*)&As[buf][kk][64 + (ty << 2)];
            float4 b0 = *(const float4*)&Bs[buf][kk][tx << 2];
            float4 b1 = *(const float4*)&Bs[buf][kk][64 + (tx << 2)];
            ull bb[8] = {pk2(b0.x, b0.x), pk2(b0.y, b0.y),
                         pk2(b0.z, b0.z), pk2(b0.w, b0.w),
                         pk2(b1.x, b1.x), pk2(b1.y, b1.y),
                         pk2(b1.z, b1.z), pk2(b1.w, b1.w)};
            ull aa[4] = {ap0.x, ap0.y, ap1.x, ap1.y};
#pragma unroll
            for (int rp = 0; rp < 4; rp++)
#pragma unroll
                for (int j = 0; j < 8; j++) ffma2(acc[rp][j], aa[rp], bb[j]);
        }
        if (more) {
            int nb = buf ^ 1;
            As[nb][a_c4 + 0][a_r] = ra0.x; As[nb][a_c4 + 1][a_r] = ra0.y;
            As[nb][a_c4 + 2][a_r] = ra0.z; As[nb][a_c4 + 3][a_r] = ra0.w;
            As[nb][a_c4 + 0][a_r + 64] = ra1.x; As[nb][a_c4 + 1][a_r + 64] = ra1.y;
            As[nb][a_c4 + 2][a_r + 64] = ra1.z; As[nb][a_c4 + 3][a_r + 64] = ra1.w;
            if (BT) {
                Bs[nb][a_c4 + 0][a_r] = rb0.x; Bs[nb][a_c4 + 1][a_r] = rb0.y;
                Bs[nb][a_c4 + 2][a_r] = rb0.z; Bs[nb][a_c4 + 3][a_r] = rb0.w;
                Bs[nb][a_c4 + 0][a_r + 64] = rb1.x; Bs[nb][a_c4 + 1][a_r + 64] = rb1.y;
                Bs[nb][a_c4 + 2][a_r + 64] = rb1.z; Bs[nb][a_c4 + 3][a_r + 64] = rb1.w;
            } else {
                *(float4*)&Bs[nb][b_k][b_n4] = rb0;
                *(float4*)&Bs[nb][b_k + 8][b_n4] = rb1;
            }
        }
        __syncthreads();
        buf ^= 1;
    }
}

// row base inside 128 tile for acc row-pair rp
__device__ __forceinline__ int pair_row(int rp, int ty) {
    return ((rp >> 1) << 6) + (ty << 2) + ((rp & 1) << 1);
}

// ---------------------------------------------------------------------------
// Kernel 1: fused QKV projection. grid (4, 16, 24), 256 thr.
// ---------------------------------------------------------------------------
__global__ void __launch_bounds__(256, 2) proj_kernel(
    const float* __restrict__ x,
    const float* __restrict__ Wq, const float* __restrict__ bq,
    const float* __restrict__ Wk, const float* __restrict__ bk,
    const float* __restrict__ Wv, const float* __restrict__ bv)
{
    __shared__ __align__(16) float As[2][16][128];
    __shared__ __align__(16) float Bs[2][16][128];

    int zb = blockIdx.z;
    int b = zb / 3, p = zb % 3;
    const float* W    = (p == 0) ? Wq : (p == 1) ? Wk : Wv;
    const float* bias = (p == 0) ? bq : (p == 1) ? bk : bv;
    float* out = ((p == 0) ? g_q : (p == 1) ? g_k : g_v) + (size_t)b * EE * DD;

    int m0 = blockIdx.y * 128, n0 = blockIdx.x * 128;

    ull acc[4][8];
#pragma unroll
    for (int i = 0; i < 4; i++)
#pragma unroll
        for (int j = 0; j < 8; j++) acc[i][j] = 0ull;

    mm_tile<false>(x + (size_t)b * EE * DD + (size_t)m0 * DD, DD,
                   W + n0, DD, DD, As, Bs, acc);

    int tx = threadIdx.x & 15, ty = threadIdx.x >> 4;
    float4 bias0 = *(const float4*)(bias + n0 + (tx << 2));
    float4 bias1 = *(const float4*)(bias + n0 + 64 + (tx << 2));
    float bb0[4] = {bias0.x, bias0.y, bias0.z, bias0.w};
    float bb1[4] = {bias1.x, bias1.y, bias1.z, bias1.w};
#pragma unroll
    for (int rp = 0; rp < 4; rp++) {
        int r = m0 + pair_row(rp, ty);
        float2 c[8];
#pragma unroll
        for (int j = 0; j < 8; j++) c[j] = upk2(acc[rp][j]);
        float4 lo0 = {c[0].x + bb0[0], c[1].x + bb0[1], c[2].x + bb0[2], c[3].x + bb0[3]};
        float4 lo1 = {c[4].x + bb1[0], c[5].x + bb1[1], c[6].x + bb1[2], c[7].x + bb1[3]};
        float4 hi0 = {c[0].y + bb0[0], c[1].y + bb0[1], c[2].y + bb0[2], c[3].y + bb0[3]};
        float4 hi1 = {c[4].y + bb1[0], c[5].y + bb1[1], c[6].y + bb1[2], c[7].y + bb1[3]};
        *(float4*)(out + (size_t)r * DD + n0 + (tx << 2)) = lo0;
        *(float4*)(out + (size_t)r * DD + n0 + 64 + (tx << 2)) = lo1;
        *(float4*)(out + (size_t)(r + 1) * DD + n0 + (tx << 2)) = hi0;
        *(float4*)(out + (size_t)(r + 1) * DD + n0 + 64 + (tx << 2)) = hi1;
    }
}

// ---------------------------------------------------------------------------
// Kernel 2: scores. grid (16, 16, 8), 256 thr.
// ---------------------------------------------------------------------------
__global__ void __launch_bounds__(256, 2) scores_kernel(
    const float* __restrict__ qa, const float* __restrict__ ka,
    const int* __restrict__ adj, const float* __restrict__ mc,
    const float* __restrict__ thr_p)
{
    __shared__ __align__(16) float As[2][16][128];
    __shared__ __align__(16) float Bs[2][16][128];

    int b = blockIdx.z;
    int m0 = blockIdx.y * 128, n0 = blockIdx.x * 128;

    ull acc[4][8], acc2[4][8];
#pragma unroll
    for (int i = 0; i < 4; i++)
#pragma unroll
        for (int j = 0; j < 8; j++) { acc[i][j] = 0ull; acc2[i][j] = 0ull; }

    mm_tile<true>(g_q + (size_t)b * EE * DD + (size_t)m0 * DD, DD,
                  g_k + (size_t)b * EE * DD + (size_t)n0 * DD, DD,
                  DD, As, Bs, acc);
    mm_tile<true>(qa + (size_t)b * EE * DA + (size_t)m0 * DA, DA,
                  ka + (size_t)b * EE * DA + (size_t)n0 * DA, DA,
                  DA, As, Bs, acc2);

    float* S = g_s + (size_t)b * EE * EE;
    const int*   AD = adj + (size_t)b * EE * EE;
    const float* MC = mc  + (size_t)b * EE * EE;
    float thr = *thr_p;
    const float inv_sq = 1.0f / 22.627416997969522f;  // 1/sqrt(512)

    int tx = threadIdx.x & 15, ty = threadIdx.x >> 4;
#pragma unroll
    for (int rp = 0; rp < 4; rp++) {
        int rbase = m0 + pair_row(rp, ty);
        float2 c[8], c2[8];
#pragma unroll
        for (int j = 0; j < 8; j++) { c[j] = upk2(acc[rp][j]); c2[j] = upk2(acc2[rp][j]); }
#pragma unroll
        for (int lane = 0; lane < 2; lane++) {
            int e = rbase + lane;
#pragma unroll
            for (int half = 0; half < 2; half++) {
                int f = n0 + half * 64 + (tx << 2);
                int4   ad = *(const int4*)(AD + (size_t)e * EE + f);
                float4 cc = *(const float4*)(MC + (size_t)e * EE + f);
                int   adr[4] = {ad.x, ad.y, ad.z, ad.w};
                float ccr[4] = {cc.x, cc.y, cc.z, cc.w};
                float outr[4];
#pragma unroll
                for (int j = 0; j < 4; j++) {
                    int jj = half * 4 + j;
                    float s  = (lane ? c[jj].y : c[jj].x) * inv_sq;
                    float sa = (lane ? c2[jj].y : c2[jj].x) * 0.125f;
                    bool merge = (s > thr) && (sa != 0.0f);
                    float co = ccr[j];
                    float r = merge ? (1.0f - co) * s + co * sa : s;
                    if (adr[j] == 0) r = -FLT_MAX;
                    outr[j] = r;
                }
                float4 o = {outr[0], outr[1], outr[2], outr[3]};
                *(float4*)(S + (size_t)e * EE + f) = o;
            }
        }
    }
}

// ---------------------------------------------------------------------------
// Kernel 3: row softmax, one block per row of length 2048.
// ---------------------------------------------------------------------------
__global__ void __launch_bounds__(256) softmax_kernel()
{
    size_t row = blockIdx.x;
    float* S = g_s + row * EE;
    int tid = threadIdx.x;

    float v[8];
    float m = -FLT_MAX;
#pragma unroll
    for (int i = 0; i < 8; i++) {
        v[i] = S[tid + i * 256];
        m = fmaxf(m, v[i]);
    }
    __shared__ float redm[8];
    __shared__ float reds[8];
#pragma unroll
    for (int o = 16; o > 0; o >>= 1) m = fmaxf(m, __shfl_xor_sync(~0u, m, o));
    if ((tid & 31) == 0) redm[tid >> 5] = m;
    __syncthreads();
#pragma unroll
    for (int i = 0; i < 8; i++) m = fmaxf(m, redm[i]);

    float s = 0.f;
#pragma unroll
    for (int i = 0; i < 8; i++) {
        v[i] = __expf(v[i] - m);
        s += v[i];
    }
#pragma unroll
    for (int o = 16; o > 0; o >>= 1) s += __shfl_xor_sync(~0u, s, o);
    if ((tid & 31) == 0) reds[tid >> 5] = s;
    __syncthreads();
    s = 0.f;
#pragma unroll
    for (int i = 0; i < 8; i++) s += reds[i];

    float inv = 1.0f / s;
#pragma unroll
    for (int i = 0; i < 8; i++) S[tid + i * 256] = v[i] * inv;
}

// ---------------------------------------------------------------------------
// Kernel 4: out = attn @ v. grid (4, 16, 8), 256 thr. GEMM-NN K=2048.
// ---------------------------------------------------------------------------
__global__ void __launch_bounds__(256, 2) av_kernel(float* __restrict__ out)
{
    __shared__ __align__(16) float As[2][16][128];
    __shared__ __align__(16) float Bs[2][16][128];

    int b = blockIdx.z;
    int m0 = blockIdx.y * 128, n0 = blockIdx.x * 128;
    float* C = out + (size_t)b * EE * DD;

    ull acc[4][8];
#pragma unroll
    for (int i = 0; i < 4; i++)
#pragma unroll
        for (int j = 0; j < 8; j++) acc[i][j] = 0ull;

    mm_tile<false>(g_s + (size_t)b * EE * EE + (size_t)m0 * EE, EE,
                   g_v + (size_t)b * EE * DD + n0, DD, EE, As, Bs, acc);

    int tx = threadIdx.x & 15, ty = threadIdx.x >> 4;
#pragma unroll
    for (int rp = 0; rp < 4; rp++) {
        int r = m0 + pair_row(rp, ty);
        float2 c[8];
#pragma unroll
        for (int j = 0; j < 8; j++) c[j] = upk2(acc[rp][j]);
        float4 lo0 = {c[0].x, c[1].x, c[2].x, c[3].x};
        float4 lo1 = {c[4].x, c[5].x, c[6].x, c[7].x};
        float4 hi0 = {c[0].y, c[1].y, c[2].y, c[3].y};
        float4 hi1 = {c[4].y, c[5].y, c[6].y, c[7].y};
        *(float4*)(C + (size_t)r * DD + n0 + (tx << 2)) = lo0;
        *(float4*)(C + (size_t)r * DD + n0 + 64 + (tx << 2)) = lo1;
        *(float4*)(C + (size_t)(r + 1) * DD + n0 + (tx << 2)) = hi0;
        *(float4*)(C + (size_t)(r + 1) * DD + n0 + 64 + (tx << 2)) = hi1;
    }
}

// ---------------------------------------------------------------------------
extern "C" void kernel_launch(void* const* d_in, const int* in_sizes, int n_in,
                              void* d_out, int out_size)
{
    const float* x   = (const float*)d_in[0];
    const float* qa  = (const float*)d_in[1];
    const float* ka  = (const float*)d_in[2];
    const int*   adj = (const int*)  d_in[3];
    const float* mc  = (const float*)d_in[4];
    const float* Wq  = (const float*)d_in[5];
    const float* bq  = (const float*)d_in[6];
    const float* Wk  = (const float*)d_in[7];
    const float* bk  = (const float*)d_in[8];
    const float* Wv  = (const float*)d_in[9];
    const float* bv  = (const float*)d_in[10];
    const float* thr = (const float*)d_in[11];

    dim3 blk(256);
    proj_kernel<<<dim3(DD / 128, EE / 128, BB * 3), blk>>>(x, Wq, bq, Wk, bk, Wv, bv);
    scores_kernel<<<dim3(EE / 128, EE / 128, BB), blk>>>(qa, ka, adj, mc, thr);
    softmax_kernel<<<BB * EE, 256>>>();
    av_kernel<<<dim3(DD / 128, EE / 128, BB), blk>>>((float*)d_out);
}

// round 5
// speedup vs baseline: 1.1057x; 1.1057x over previous
#include <cuda_runtime.h>
#include <math.h>
#include <float.h>

#define BB 8
#define EE 2048
#define DD 512
#define DA 64

typedef unsigned long long ull;

// Scratch (static __device__ arrays: allocation-guard safe)
__device__ float g_q[BB * EE * DD];
__device__ float g_k[BB * EE * DD];
__device__ float g_v[BB * EE * DD];
__device__ float g_s[(size_t)BB * EE * EE];

// bank-conflict-killing XOR swizzle: row r (0..15), float col c (0..127)
// swizzled col = c ^ (((r>>2)&3)<<3).  Multiple of 8 floats -> 16B vector
// loads/stores stay aligned; the four k-row groups of the transpose store
// land in four disjoint 8-bank windows (conflict-free).
#define SW(r) ((((r) >> 2) & 3) << 3)

// ---------------------------------------------------------------------------
// packed f32x2 helpers
// ---------------------------------------------------------------------------
__device__ __forceinline__ ull pk2(float lo, float hi) {
    ull r;
    asm("mov.b64 %0, {%1,%2};" : "=l"(r) : "f"(lo), "f"(hi));
    return r;
}
__device__ __forceinline__ void ffma2(ull& c, ull a, ull b) {
    asm("fma.rn.f32x2 %0, %1, %2, %0;" : "+l"(c) : "l"(a), "l"(b));
}
__device__ __forceinline__ float2 upk2(ull v) {
    float2 f;
    asm("mov.b64 {%0,%1}, %2;" : "=f"(f.x), "=f"(f.y) : "l"(v));
    return f;
}

// ---------------------------------------------------------------------------
// 128x128 tile GEMM core, 8x8 per thread, f32x2 FMA, double-buffered smem,
// swizzled tiles. acc[rp][j]: rp = 4 row-pairs (f32x2 lanes = rows), j = 8 cols.
// ---------------------------------------------------------------------------
template <bool BT>
__device__ __forceinline__ void mm_tile(
    const float* __restrict__ A, int lda,
    const float* __restrict__ B, int ldb,
    int Ktot, float (*As)[16][128], float (*Bs)[16][128], ull acc[4][8])
{
    const int t = threadIdx.x;
    const int a_c4 = (t & 3) << 2;   // k offset within chunk: 0,4,8,12
    const int a_r  = t >> 2;         // 0..63 (rows a_r and a_r+64)
    const int b_n4 = (t & 31) << 2;  // 0..124
    const int b_k  = t >> 5;         // 0..7
    const int tx = t & 15, ty = t >> 4;
    const int xsa = a_r ^ SW(a_c4);          // swizzled col for transpose stores
    const int xb0 = b_n4 ^ SW(b_k);          // swizzled col for direct stores
    const int xb1 = b_n4 ^ SW(b_k + 8);

    float4 ra0, ra1, rb0, rb1;

    ra0 = *(const float4*)(A + (size_t)a_r * lda + a_c4);
    ra1 = *(const float4*)(A + (size_t)(a_r + 64) * lda + a_c4);
    if (BT) {
        rb0 = *(const float4*)(B + (size_t)a_r * ldb + a_c4);
        rb1 = *(const float4*)(B + (size_t)(a_r + 64) * ldb + a_c4);
    } else {
        rb0 = *(const float4*)(B + (size_t)b_k * ldb + b_n4);
        rb1 = *(const float4*)(B + (size_t)(b_k + 8) * ldb + b_n4);
    }

    int buf = 0;
    {
        As[0][a_c4 + 0][xsa] = ra0.x; As[0][a_c4 + 1][xsa] = ra0.y;
        As[0][a_c4 + 2][xsa] = ra0.z; As[0][a_c4 + 3][xsa] = ra0.w;
        As[0][a_c4 + 0][xsa + 64] = ra1.x; As[0][a_c4 + 1][xsa + 64] = ra1.y;
        As[0][a_c4 + 2][xsa + 64] = ra1.z; As[0][a_c4 + 3][xsa + 64] = ra1.w;
        if (BT) {
            Bs[0][a_c4 + 0][xsa] = rb0.x; Bs[0][a_c4 + 1][xsa] = rb0.y;
            Bs[0][a_c4 + 2][xsa] = rb0.z; Bs[0][a_c4 + 3][xsa] = rb0.w;
            Bs[0][a_c4 + 0][xsa + 64] = rb1.x; Bs[0][a_c4 + 1][xsa + 64] = rb1.y;
            Bs[0][a_c4 + 2][xsa + 64] = rb1.z; Bs[0][a_c4 + 3][xsa + 64] = rb1.w;
        } else {
            *(float4*)&Bs[0][b_k][xb0] = rb0;
            *(float4*)&Bs[0][b_k + 8][xb1] = rb1;
        }
    }
    __syncthreads();

    for (int k0 = 0; k0 < Ktot; k0 += 16) {
        const bool more = (k0 + 16) < Ktot;
        if (more) {
            int kn = k0 + 16;
            ra0 = *(const float4*)(A + (size_t)a_r * lda + kn + a_c4);
            ra1 = *(const float4*)(A + (size_t)(a_r + 64) * lda + kn + a_c4);
            if (BT) {
                rb0 = *(const float4*)(B + (size_t)a_r * ldb + kn + a_c4);
                rb1 = *(const float4*)(B + (size_t)(a_r + 64) * ldb + kn + a_c4);
            } else {
                rb0 = *(const float4*)(B + (size_t)(kn + b_k) * ldb + b_n4);
                rb1 = *(const float4*)(B + (size_t)(kn + b_k + 8) * ldb + b_n4);
            }
        }
#pragma unroll
        for (int kk = 0; kk < 16; kk++) {
            const int xr = SW(kk);
            ulonglong2 ap0 = *(const ulonglong2*)&As[buf][kk][(ty << 2) ^ xr];
            ulonglong2 ap1 = *(const ulonglong2*)&As[buf][kk][64 + ((ty << 2) ^ xr)];
            float4 b0 = *(const float4*)&Bs[buf][kk][(tx << 2) ^ xr];
            float4 b1 = *(const float4*)&Bs[buf][kk][64 + ((tx << 2) ^ xr)];
            ull bb[8] = {pk2(b0.x, b0.x), pk2(b0.y, b0.y),
                         pk2(b0.z, b0.z), pk2(b0.w, b0.w),
                         pk2(b1.x, b1.x), pk2(b1.y, b1.y),
                         pk2(b1.z, b1.z), pk2(b1.w, b1.w)};
            ull aa[4] = {ap0.x, ap0.y, ap1.x, ap1.y};
#pragma unroll
            for (int rp = 0; rp < 4; rp++)
#pragma unroll
                for (int j = 0; j < 8; j++) ffma2(acc[rp][j], aa[rp], bb[j]);
        }
        if (more) {
            int nb = buf ^ 1;
            As[nb][a_c4 + 0][xsa] = ra0.x; As[nb][a_c4 + 1][xsa] = ra0.y;
            As[nb][a_c4 + 2][xsa] = ra0.z; As[nb][a_c4 + 3][xsa] = ra0.w;
            As[nb][a_c4 + 0][xsa + 64] = ra1.x; As[nb][a_c4 + 1][xsa + 64] = ra1.y;
            As[nb][a_c4 + 2][xsa + 64] = ra1.z; As[nb][a_c4 + 3][xsa + 64] = ra1.w;
            if (BT) {
                Bs[nb][a_c4 + 0][xsa] = rb0.x; Bs[nb][a_c4 + 1][xsa] = rb0.y;
                Bs[nb][a_c4 + 2][xsa] = rb0.z; Bs[nb][a_c4 + 3][xsa] = rb0.w;
                Bs[nb][a_c4 + 0][xsa + 64] = rb1.x; Bs[nb][a_c4 + 1][xsa + 64] = rb1.y;
                Bs[nb][a_c4 + 2][xsa + 64] = rb1.z; Bs[nb][a_c4 + 3][xsa + 64] = rb1.w;
            } else {
                *(float4*)&Bs[nb][b_k][xb0] = rb0;
                *(float4*)&Bs[nb][b_k + 8][xb1] = rb1;
            }
        }
        __syncthreads();
        buf ^= 1;
    }
}

// row base inside 128 tile for acc row-pair rp
__device__ __forceinline__ int pair_row(int rp, int ty) {
    return ((rp >> 1) << 6) + (ty << 2) + ((rp & 1) << 1);
}

// ---------------------------------------------------------------------------
// Kernel 1: fused QKV projection. grid (4, 16, 24), 256 thr.
// ---------------------------------------------------------------------------
__global__ void __launch_bounds__(256, 2) proj_kernel(
    const float* __restrict__ x,
    const float* __restrict__ Wq, const float* __restrict__ bq,
    const float* __restrict__ Wk, const float* __restrict__ bk,
    const float* __restrict__ Wv, const float* __restrict__ bv)
{
    __shared__ __align__(16) float As[2][16][128];
    __shared__ __align__(16) float Bs[2][16][128];

    int zb = blockIdx.z;
    int b = zb / 3, p = zb % 3;
    const float* W    = (p == 0) ? Wq : (p == 1) ? Wk : Wv;
    const float* bias = (p == 0) ? bq : (p == 1) ? bk : bv;
    float* out = ((p == 0) ? g_q : (p == 1) ? g_k : g_v) + (size_t)b * EE * DD;

    int m0 = blockIdx.y * 128, n0 = blockIdx.x * 128;

    ull acc[4][8];
#pragma unroll
    for (int i = 0; i < 4; i++)
#pragma unroll
        for (int j = 0; j < 8; j++) acc[i][j] = 0ull;

    mm_tile<false>(x + (size_t)b * EE * DD + (size_t)m0 * DD, DD,
                   W + n0, DD, DD, As, Bs, acc);

    int tx = threadIdx.x & 15, ty = threadIdx.x >> 4;
    float4 bias0 = *(const float4*)(bias + n0 + (tx << 2));
    float4 bias1 = *(const float4*)(bias + n0 + 64 + (tx << 2));
    float bb0[4] = {bias0.x, bias0.y, bias0.z, bias0.w};
    float bb1[4] = {bias1.x, bias1.y, bias1.z, bias1.w};
#pragma unroll
    for (int rp = 0; rp < 4; rp++) {
        int r = m0 + pair_row(rp, ty);
        float2 c[8];
#pragma unroll
        for (int j = 0; j < 8; j++) c[j] = upk2(acc[rp][j]);
        float4 lo0 = {c[0].x + bb0[0], c[1].x + bb0[1], c[2].x + bb0[2], c[3].x + bb0[3]};
        float4 lo1 = {c[4].x + bb1[0], c[5].x + bb1[1], c[6].x + bb1[2], c[7].x + bb1[3]};
        float4 hi0 = {c[0].y + bb0[0], c[1].y + bb0[1], c[2].y + bb0[2], c[3].y + bb0[3]};
        float4 hi1 = {c[4].y + bb1[0], c[5].y + bb1[1], c[6].y + bb1[2], c[7].y + bb1[3]};
        *(float4*)(out + (size_t)r * DD + n0 + (tx << 2)) = lo0;
        *(float4*)(out + (size_t)r * DD + n0 + 64 + (tx << 2)) = lo1;
        *(float4*)(out + (size_t)(r + 1) * DD + n0 + (tx << 2)) = hi0;
        *(float4*)(out + (size_t)(r + 1) * DD + n0 + 64 + (tx << 2)) = hi1;
    }
}

// ---------------------------------------------------------------------------
// Kernel 2a: aux scores (K=64).  sa = QA @ KA^T / 8  -> g_s
// ---------------------------------------------------------------------------
__global__ void __launch_bounds__(256, 2) scores_aux_kernel(
    const float* __restrict__ qa, const float* __restrict__ ka)
{
    __shared__ __align__(16) float As[2][16][128];
    __shared__ __align__(16) float Bs[2][16][128];

    int b = blockIdx.z;
    int m0 = blockIdx.y * 128, n0 = blockIdx.x * 128;

    ull acc[4][8];
#pragma unroll
    for (int i = 0; i < 4; i++)
#pragma unroll
        for (int j = 0; j < 8; j++) acc[i][j] = 0ull;

    mm_tile<true>(qa + (size_t)b * EE * DA + (size_t)m0 * DA, DA,
                  ka + (size_t)b * EE * DA + (size_t)n0 * DA, DA,
                  DA, As, Bs, acc);

    float* S = g_s + (size_t)b * EE * EE;
    int tx = threadIdx.x & 15, ty = threadIdx.x >> 4;
#pragma unroll
    for (int rp = 0; rp < 4; rp++) {
        int r = m0 + pair_row(rp, ty);
        float2 c[8];
#pragma unroll
        for (int j = 0; j < 8; j++) c[j] = upk2(acc[rp][j]);
        float4 lo0 = {c[0].x * 0.125f, c[1].x * 0.125f, c[2].x * 0.125f, c[3].x * 0.125f};
        float4 lo1 = {c[4].x * 0.125f, c[5].x * 0.125f, c[6].x * 0.125f, c[7].x * 0.125f};
        float4 hi0 = {c[0].y * 0.125f, c[1].y * 0.125f, c[2].y * 0.125f, c[3].y * 0.125f};
        float4 hi1 = {c[4].y * 0.125f, c[5].y * 0.125f, c[6].y * 0.125f, c[7].y * 0.125f};
        *(float4*)(S + (size_t)r * EE + n0 + (tx << 2)) = lo0;
        *(float4*)(S + (size_t)r * EE + n0 + 64 + (tx << 2)) = lo1;
        *(float4*)(S + (size_t)(r + 1) * EE + n0 + (tx << 2)) = hi0;
        *(float4*)(S + (size_t)(r + 1) * EE + n0 + 64 + (tx << 2)) = hi1;
    }
}

// ---------------------------------------------------------------------------
// Kernel 2b: main scores = Q @ K^T / sqrt(D); blend with sa (from g_s),
// adjacency mask; write final scores to g_s.
// ---------------------------------------------------------------------------
__global__ void __launch_bounds__(256, 2) scores_main_kernel(
    const int* __restrict__ adj, const float* __restrict__ mc,
    const float* __restrict__ thr_p)
{
    __shared__ __align__(16) float As[2][16][128];
    __shared__ __align__(16) float Bs[2][16][128];

    int b = blockIdx.z;
    int m0 = blockIdx.y * 128, n0 = blockIdx.x * 128;

    ull acc[4][8];
#pragma unroll
    for (int i = 0; i < 4; i++)
#pragma unroll
        for (int j = 0; j < 8; j++) acc[i][j] = 0ull;

    mm_tile<true>(g_q + (size_t)b * EE * DD + (size_t)m0 * DD, DD,
                  g_k + (size_t)b * EE * DD + (size_t)n0 * DD, DD,
                  DD, As, Bs, acc);

    float* S = g_s + (size_t)b * EE * EE;
    const int*   AD = adj + (size_t)b * EE * EE;
    const float* MC = mc  + (size_t)b * EE * EE;
    float thr = *thr_p;
    const float inv_sq = 1.0f / 22.627416997969522f;  // 1/sqrt(512)

    int tx = threadIdx.x & 15, ty = threadIdx.x >> 4;
#pragma unroll
    for (int rp = 0; rp < 4; rp++) {
        int rbase = m0 + pair_row(rp, ty);
        float2 c[8];
#pragma unroll
        for (int j = 0; j < 8; j++) c[j] = upk2(acc[rp][j]);
#pragma unroll
        for (int lane = 0; lane < 2; lane++) {
            int e = rbase + lane;
#pragma unroll
            for (int half = 0; half < 2; half++) {
                int f = n0 + half * 64 + (tx << 2);
                float4 sa4 = *(const float4*)(S + (size_t)e * EE + f);
                int4   ad = *(const int4*)(AD + (size_t)e * EE + f);
                float4 cc = *(const float4*)(MC + (size_t)e * EE + f);
                int   adr[4] = {ad.x, ad.y, ad.z, ad.w};
                float ccr[4] = {cc.x, cc.y, cc.z, cc.w};
                float sar[4] = {sa4.x, sa4.y, sa4.z, sa4.w};
                float outr[4];
#pragma unroll
                for (int j = 0; j < 4; j++) {
                    int jj = half * 4 + j;
                    float s  = (lane ? c[jj].y : c[jj].x) * inv_sq;
                    float sa = sar[j];
                    bool merge = (s > thr) && (sa != 0.0f);
                    float co = ccr[j];
                    float r = merge ? (1.0f - co) * s + co * sa : s;
                    if (adr[j] == 0) r = -FLT_MAX;
                    outr[j] = r;
                }
                float4 o = {outr[0], outr[1], outr[2], outr[3]};
                *(float4*)(S + (size_t)e * EE + f) = o;
            }
        }
    }
}

// ---------------------------------------------------------------------------
// Kernel 3: row softmax, one block per row of length 2048.
// ---------------------------------------------------------------------------
__global__ void __launch_bounds__(256) softmax_kernel()
{
    size_t row = blockIdx.x;
    float* S = g_s + row * EE;
    int tid = threadIdx.x;

    float v[8];
    float m = -FLT_MAX;
#pragma unroll
    for (int i = 0; i < 8; i++) {
        v[i] = S[tid + i * 256];
        m = fmaxf(m, v[i]);
    }
    __shared__ float redm[8];
    __shared__ float reds[8];
#pragma unroll
    for (int o = 16; o > 0; o >>= 1) m = fmaxf(m, __shfl_xor_sync(~0u, m, o));
    if ((tid & 31) == 0) redm[tid >> 5] = m;
    __syncthreads();
#pragma unroll
    for (int i = 0; i < 8; i++) m = fmaxf(m, redm[i]);

    float s = 0.f;
#pragma unroll
    for (int i = 0; i < 8; i++) {
        v[i] = __expf(v[i] - m);
        s += v[i];
    }
#pragma unroll
    for (int o = 16; o > 0; o >>= 1) s += __shfl_xor_sync(~0u, s, o);
    if ((tid & 31) == 0) reds[tid >> 5] = s;
    __syncthreads();
    s = 0.f;
#pragma unroll
    for (int i = 0; i < 8; i++) s += reds[i];

    float inv = 1.0f / s;
#pragma unroll
    for (int i = 0; i < 8; i++) S[tid + i * 256] = v[i] * inv;
}

// ---------------------------------------------------------------------------
// Kernel 4: out = attn @ v. grid (4, 16, 8), 256 thr. GEMM-NN K=2048.
// ---------------------------------------------------------------------------
__global__ void __launch_bounds__(256, 2) av_kernel(float* __restrict__ out)
{
    __shared__ __align__(16) float As[2][16][128];
    __shared__ __align__(16) float Bs[2][16][128];

    int b = blockIdx.z;
    int m0 = blockIdx.y * 128, n0 = blockIdx.x * 128;
    float* C = out + (size_t)b * EE * DD;

    ull acc[4][8];
#pragma unroll
    for (int i = 0; i < 4; i++)
#pragma unroll
        for (int j = 0; j < 8; j++) acc[i][j] = 0ull;

    mm_tile<false>(g_s + (size_t)b * EE * EE + (size_t)m0 * EE, EE,
                   g_v + (size_t)b * EE * DD + n0, DD, EE, As, Bs, acc);

    int tx = threadIdx.x & 15, ty = threadIdx.x >> 4;
#pragma unroll
    for (int rp = 0; rp < 4; rp++) {
        int r = m0 + pair_row(rp, ty);
        float2 c[8];
#pragma unroll
        for (int j = 0; j < 8; j++) c[j] = upk2(acc[rp][j]);
        float4 lo0 = {c[0].x, c[1].x, c[2].x, c[3].x};
        float4 lo1 = {c[4].x, c[5].x, c[6].x, c[7].x};
        float4 hi0 = {c[0].y, c[1].y, c[2].y, c[3].y};
        float4 hi1 = {c[4].y, c[5].y, c[6].y, c[7].y};
        *(float4*)(C + (size_t)r * DD + n0 + (tx << 2)) = lo0;
        *(float4*)(C + (size_t)r * DD + n0 + 64 + (tx << 2)) = lo1;
        *(float4*)(C + (size_t)(r + 1) * DD + n0 + (tx << 2)) = hi0;
        *(float4*)(C + (size_t)(r + 1) * DD + n0 + 64 + (tx << 2)) = hi1;
    }
}

// ---------------------------------------------------------------------------
extern "C" void kernel_launch(void* const* d_in, const int* in_sizes, int n_in,
                              void* d_out, int out_size)
{
    const float* x   = (const float*)d_in[0];
    const float* qa  = (const float*)d_in[1];
    const float* ka  = (const float*)d_in[2];
    const int*   adj = (const int*)  d_in[3];
    const float* mc  = (const float*)d_in[4];
    const float* Wq  = (const float*)d_in[5];
    const float* bq  = (const float*)d_in[6];
    const float* Wk  = (const float*)d_in[7];
    const float* bk  = (const float*)d_in[8];
    const float* Wv  = (const float*)d_in[9];
    const float* bv  = (const float*)d_in[10];
    const float* thr = (const float*)d_in[11];

    dim3 blk(256);
    proj_kernel<<<dim3(DD / 128, EE / 128, BB * 3), blk>>>(x, Wq, bq, Wk, bk, Wv, bv);
    scores_aux_kernel<<<dim3(EE / 128, EE / 128, BB), blk>>>(qa, ka);
    scores_main_kernel<<<dim3(EE / 128, EE / 128, BB), blk>>>(adj, mc, thr);
    softmax_kernel<<<BB * EE, 256>>>();
    av_kernel<<<dim3(DD / 128, EE / 128, BB), blk>>>((float*)d_out);
}

// round 7
// speedup vs baseline: 1.5003x; 1.3569x over previous
#include <cuda_runtime.h>
#include <cuda_fp16.h>
#include <math.h>
#include <float.h>
#include <cstdint>

#define BB 8
#define EE 2048
#define DD 512
#define DA 64

typedef unsigned long long ull;

// Scratch (static __device__ arrays: allocation-guard safe)
__device__ float g_q[BB * EE * DD];
__device__ float g_k[BB * EE * DD];
__device__ float g_v[BB * EE * DD];
__device__ float g_s[(size_t)BB * EE * EE];
__device__ __half g_s16[(size_t)BB * EE * EE];   // fp16 attn probs
__device__ __half g_vt16[(size_t)BB * DD * EE];  // fp16 V^T, [b][n][k]

// smem XOR swizzle for the SIMT GEMM tiles
#define SW(r) ((((r) >> 2) & 3) << 3)
// SW128 byte swizzle for 128B-row fp16 tiles (ldmatrix-friendly)
#define SW128B(o) ((o) ^ (((o) >> 3) & 0x70))

// ---------------------------------------------------------------------------
// packed f32x2 helpers
// ---------------------------------------------------------------------------
__device__ __forceinline__ ull pk2(float lo, float hi) {
    ull r;
    asm("mov.b64 %0, {%1,%2};" : "=l"(r) : "f"(lo), "f"(hi));
    return r;
}
__device__ __forceinline__ void ffma2(ull& c, ull a, ull b) {
    asm("fma.rn.f32x2 %0, %1, %2, %0;" : "+l"(c) : "l"(a), "l"(b));
}
__device__ __forceinline__ float2 upk2(ull v) {
    float2 f;
    asm("mov.b64 {%0,%1}, %2;" : "=f"(f.x), "=f"(f.y) : "l"(v));
    return f;
}
__device__ __forceinline__ uint32_t smem_u32(const void* p) {
    uint32_t a;
    asm("{ .reg .u64 t; cvta.to.shared.u64 t, %1; cvt.u32.u64 %0, t; }"
        : "=r"(a) : "l"(p));
    return a;
}

// ---------------------------------------------------------------------------
// SIMT 128x128 tile GEMM core (f32x2), double-buffered + swizzled.
// ---------------------------------------------------------------------------
template <bool BT>
__device__ __forceinline__ void mm_tile(
    const float* __restrict__ A, int lda,
    const float* __restrict__ B, int ldb,
    int Ktot, float (*As)[16][128], float (*Bs)[16][128], ull acc[4][8])
{
    const int t = threadIdx.x;
    const int a_c4 = (t & 3) << 2;
    const int a_r  = t >> 2;
    const int b_n4 = (t & 31) << 2;
    const int b_k  = t >> 5;
    const int tx = t & 15, ty = t >> 4;
    const int xsa = a_r ^ SW(a_c4);
    const int xb0 = b_n4 ^ SW(b_k);
    const int xb1 = b_n4 ^ SW(b_k + 8);

    float4 ra0, ra1, rb0, rb1;

    ra0 = *(const float4*)(A + (size_t)a_r * lda + a_c4);
    ra1 = *(const float4*)(A + (size_t)(a_r + 64) * lda + a_c4);
    if (BT) {
        rb0 = *(const float4*)(B + (size_t)a_r * ldb + a_c4);
        rb1 = *(const float4*)(B + (size_t)(a_r + 64) * ldb + a_c4);
    } else {
        rb0 = *(const float4*)(B + (size_t)b_k * ldb + b_n4);
        rb1 = *(const float4*)(B + (size_t)(b_k + 8) * ldb + b_n4);
    }

    int buf = 0;
    {
        As[0][a_c4 + 0][xsa] = ra0.x; As[0][a_c4 + 1][xsa] = ra0.y;
        As[0][a_c4 + 2][xsa] = ra0.z; As[0][a_c4 + 3][xsa] = ra0.w;
        As[0][a_c4 + 0][xsa + 64] = ra1.x; As[0][a_c4 + 1][xsa + 64] = ra1.y;
        As[0][a_c4 + 2][xsa + 64] = ra1.z; As[0][a_c4 + 3][xsa + 64] = ra1.w;
        if (BT) {
            Bs[0][a_c4 + 0][xsa] = rb0.x; Bs[0][a_c4 + 1][xsa] = rb0.y;
            Bs[0][a_c4 + 2][xsa] = rb0.z; Bs[0][a_c4 + 3][xsa] = rb0.w;
            Bs[0][a_c4 + 0][xsa + 64] = rb1.x; Bs[0][a_c4 + 1][xsa + 64] = rb1.y;
            Bs[0][a_c4 + 2][xsa + 64] = rb1.z; Bs[0][a_c4 + 3][xsa + 64] = rb1.w;
        } else {
            *(float4*)&Bs[0][b_k][xb0] = rb0;
            *(float4*)&Bs[0][b_k + 8][xb1] = rb1;
        }
    }
    __syncthreads();

    for (int k0 = 0; k0 < Ktot; k0 += 16) {
        const bool more = (k0 + 16) < Ktot;
        if (more) {
            int kn = k0 + 16;
            ra0 = *(const float4*)(A + (size_t)a_r * lda + kn + a_c4);
            ra1 = *(const float4*)(A + (size_t)(a_r + 64) * lda + kn + a_c4);
            if (BT) {
                rb0 = *(const float4*)(B + (size_t)a_r * ldb + kn + a_c4);
                rb1 = *(const float4*)(B + (size_t)(a_r + 64) * ldb + kn + a_c4);
            } else {
                rb0 = *(const float4*)(B + (size_t)(kn + b_k) * ldb + b_n4);
                rb1 = *(const float4*)(B + (size_t)(kn + b_k + 8) * ldb + b_n4);
            }
        }
#pragma unroll
        for (int kk = 0; kk < 16; kk++) {
            const int xr = SW(kk);
            ulonglong2 ap0 = *(const ulonglong2*)&As[buf][kk][(ty << 2) ^ xr];
            ulonglong2 ap1 = *(const ulonglong2*)&As[buf][kk][64 + ((ty << 2) ^ xr)];
            float4 b0 = *(const float4*)&Bs[buf][kk][(tx << 2) ^ xr];
            float4 b1 = *(const float4*)&Bs[buf][kk][64 + ((tx << 2) ^ xr)];
            ull bb[8] = {pk2(b0.x, b0.x), pk2(b0.y, b0.y),
                         pk2(b0.z, b0.z), pk2(b0.w, b0.w),
                         pk2(b1.x, b1.x), pk2(b1.y, b1.y),
                         pk2(b1.z, b1.z), pk2(b1.w, b1.w)};
            ull aa[4] = {ap0.x, ap0.y, ap1.x, ap1.y};
#pragma unroll
            for (int rp = 0; rp < 4; rp++)
#pragma unroll
                for (int j = 0; j < 8; j++) ffma2(acc[rp][j], aa[rp], bb[j]);
        }
        if (more) {
            int nb = buf ^ 1;
            As[nb][a_c4 + 0][xsa] = ra0.x; As[nb][a_c4 + 1][xsa] = ra0.y;
            As[nb][a_c4 + 2][xsa] = ra0.z; As[nb][a_c4 + 3][xsa] = ra0.w;
            As[nb][a_c4 + 0][xsa + 64] = ra1.x; As[nb][a_c4 + 1][xsa + 64] = ra1.y;
            As[nb][a_c4 + 2][xsa + 64] = ra1.z; As[nb][a_c4 + 3][xsa + 64] = ra1.w;
            if (BT) {
                Bs[nb][a_c4 + 0][xsa] = rb0.x; Bs[nb][a_c4 + 1][xsa] = rb0.y;
                Bs[nb][a_c4 + 2][xsa] = rb0.z; Bs[nb][a_c4 + 3][xsa] = rb0.w;
                Bs[nb][a_c4 + 0][xsa + 64] = rb1.x; Bs[nb][a_c4 + 1][xsa + 64] = rb1.y;
                Bs[nb][a_c4 + 2][xsa + 64] = rb1.z; Bs[nb][a_c4 + 3][xsa + 64] = rb1.w;
            } else {
                *(float4*)&Bs[nb][b_k][xb0] = rb0;
                *(float4*)&Bs[nb][b_k + 8][xb1] = rb1;
            }
        }
        __syncthreads();
        buf ^= 1;
    }
}

__device__ __forceinline__ int pair_row(int rp, int ty) {
    return ((rp >> 1) << 6) + (ty << 2) + ((rp & 1) << 1);
}

// ---------------------------------------------------------------------------
// Kernel 1: fused QKV projection (fp32 SIMT — feeds threshold-sensitive path)
// ---------------------------------------------------------------------------
__global__ void __launch_bounds__(256, 2) proj_kernel(
    const float* __restrict__ x,
    const float* __restrict__ Wq, const float* __restrict__ bq,
    const float* __restrict__ Wk, const float* __restrict__ bk,
    const float* __restrict__ Wv, const float* __restrict__ bv)
{
    __shared__ __align__(16) float As[2][16][128];
    __shared__ __align__(16) float Bs[2][16][128];

    int zb = blockIdx.z;
    int b = zb / 3, p = zb % 3;
    const float* W    = (p == 0) ? Wq : (p == 1) ? Wk : Wv;
    const float* bias = (p == 0) ? bq : (p == 1) ? bk : bv;
    float* out = ((p == 0) ? g_q : (p == 1) ? g_k : g_v) + (size_t)b * EE * DD;

    int m0 = blockIdx.y * 128, n0 = blockIdx.x * 128;

    ull acc[4][8];
#pragma unroll
    for (int i = 0; i < 4; i++)
#pragma unroll
        for (int j = 0; j < 8; j++) acc[i][j] = 0ull;

    mm_tile<false>(x + (size_t)b * EE * DD + (size_t)m0 * DD, DD,
                   W + n0, DD, DD, As, Bs, acc);

    int tx = threadIdx.x & 15, ty = threadIdx.x >> 4;
    float4 bias0 = *(const float4*)(bias + n0 + (tx << 2));
    float4 bias1 = *(const float4*)(bias + n0 + 64 + (tx << 2));
    float bb0[4] = {bias0.x, bias0.y, bias0.z, bias0.w};
    float bb1[4] = {bias1.x, bias1.y, bias1.z, bias1.w};
#pragma unroll
    for (int rp = 0; rp < 4; rp++) {
        int r = m0 + pair_row(rp, ty);
        float2 c[8];
#pragma unroll
        for (int j = 0; j < 8; j++) c[j] = upk2(acc[rp][j]);
        float4 lo0 = {c[0].x + bb0[0], c[1].x + bb0[1], c[2].x + bb0[2], c[3].x + bb0[3]};
        float4 lo1 = {c[4].x + bb1[0], c[5].x + bb1[1], c[6].x + bb1[2], c[7].x + bb1[3]};
        float4 hi0 = {c[0].y + bb0[0], c[1].y + bb0[1], c[2].y + bb0[2], c[3].y + bb0[3]};
        float4 hi1 = {c[4].y + bb1[0], c[5].y + bb1[1], c[6].y + bb1[2], c[7].y + bb1[3]};
        *(float4*)(out + (size_t)r * DD + n0 + (tx << 2)) = lo0;
        *(float4*)(out + (size_t)r * DD + n0 + 64 + (tx << 2)) = lo1;
        *(float4*)(out + (size_t)(r + 1) * DD + n0 + (tx << 2)) = hi0;
        *(float4*)(out + (size_t)(r + 1) * DD + n0 + 64 + (tx << 2)) = hi1;
    }
}

// ---------------------------------------------------------------------------
// Kernel 1b: V transpose + fp16 convert.  g_v[b][k][n] -> g_vt16[b][n][k]
// ---------------------------------------------------------------------------
__global__ void __launch_bounds__(256) vt_kernel()
{
    __shared__ float tile[32][33];
    int b = blockIdx.z;
    int n0 = blockIdx.x * 32, k0 = blockIdx.y * 32;
    int tx = threadIdx.x & 31, ty = threadIdx.x >> 5;  // 32 x 8
    const float* V = g_v + (size_t)b * EE * DD;
    __half* VT = g_vt16 + (size_t)b * DD * EE;
#pragma unroll
    for (int i = 0; i < 4; i++)
        tile[ty + i * 8][tx] = V[(size_t)(k0 + ty + i * 8) * DD + n0 + tx];
    __syncthreads();
#pragma unroll
    for (int i = 0; i < 4; i++)
        VT[(size_t)(n0 + ty + i * 8) * EE + k0 + tx] =
            __float2half_rn(tile[tx][ty + i * 8]);
}

// ---------------------------------------------------------------------------
// Kernel 2a: aux scores (K=64).  sa = QA @ KA^T / 8  -> g_s
// ---------------------------------------------------------------------------
__global__ void __launch_bounds__(256, 2) scores_aux_kernel(
    const float* __restrict__ qa, const float* __restrict__ ka)
{
    __shared__ __align__(16) float As[2][16][128];
    __shared__ __align__(16) float Bs[2][16][128];

    int b = blockIdx.z;
    int m0 = blockIdx.y * 128, n0 = blockIdx.x * 128;

    ull acc[4][8];
#pragma unroll
    for (int i = 0; i < 4; i++)
#pragma unroll
        for (int j = 0; j < 8; j++) acc[i][j] = 0ull;

    mm_tile<true>(qa + (size_t)b * EE * DA + (size_t)m0 * DA, DA,
                  ka + (size_t)b * EE * DA + (size_t)n0 * DA, DA,
                  DA, As, Bs, acc);

    float* S = g_s + (size_t)b * EE * EE;
    int tx = threadIdx.x & 15, ty = threadIdx.x >> 4;
#pragma unroll
    for (int rp = 0; rp < 4; rp++) {
        int r = m0 + pair_row(rp, ty);
        float2 c[8];
#pragma unroll
        for (int j = 0; j < 8; j++) c[j] = upk2(acc[rp][j]);
        float4 lo0 = {c[0].x * 0.125f, c[1].x * 0.125f, c[2].x * 0.125f, c[3].x * 0.125f};
        float4 lo1 = {c[4].x * 0.125f, c[5].x * 0.125f, c[6].x * 0.125f, c[7].x * 0.125f};
        float4 hi0 = {c[0].y * 0.125f, c[1].y * 0.125f, c[2].y * 0.125f, c[3].y * 0.125f};
        float4 hi1 = {c[4].y * 0.125f, c[5].y * 0.125f, c[6].y * 0.125f, c[7].y * 0.125f};
        *(float4*)(S + (size_t)r * EE + n0 + (tx << 2)) = lo0;
        *(float4*)(S + (size_t)r * EE + n0 + 64 + (tx << 2)) = lo1;
        *(float4*)(S + (size_t)(r + 1) * EE + n0 + (tx << 2)) = hi0;
        *(float4*)(S + (size_t)(r + 1) * EE + n0 + 64 + (tx << 2)) = hi1;
    }
}

// ---------------------------------------------------------------------------
// Kernel 2b: main scores + blend + adjacency mask
// ---------------------------------------------------------------------------
__global__ void __launch_bounds__(256, 2) scores_main_kernel(
    const int* __restrict__ adj, const float* __restrict__ mc,
    const float* __restrict__ thr_p)
{
    __shared__ __align__(16) float As[2][16][128];
    __shared__ __align__(16) float Bs[2][16][128];

    int b = blockIdx.z;
    int m0 = blockIdx.y * 128, n0 = blockIdx.x * 128;

    ull acc[4][8];
#pragma unroll
    for (int i = 0; i < 4; i++)
#pragma unroll
        for (int j = 0; j < 8; j++) acc[i][j] = 0ull;

    mm_tile<true>(g_q + (size_t)b * EE * DD + (size_t)m0 * DD, DD,
                  g_k + (size_t)b * EE * DD + (size_t)n0 * DD, DD,
                  DD, As, Bs, acc);

    float* S = g_s + (size_t)b * EE * EE;
    const int*   AD = adj + (size_t)b * EE * EE;
    const float* MC = mc  + (size_t)b * EE * EE;
    float thr = *thr_p;
    const float inv_sq = 1.0f / 22.627416997969522f;

    int tx = threadIdx.x & 15, ty = threadIdx.x >> 4;
#pragma unroll
    for (int rp = 0; rp < 4; rp++) {
        int rbase = m0 + pair_row(rp, ty);
        float2 c[8];
#pragma unroll
        for (int j = 0; j < 8; j++) c[j] = upk2(acc[rp][j]);
#pragma unroll
        for (int lane = 0; lane < 2; lane++) {
            int e = rbase + lane;
#pragma unroll
            for (int half = 0; half < 2; half++) {
                int f = n0 + half * 64 + (tx << 2);
                float4 sa4 = *(const float4*)(S + (size_t)e * EE + f);
                int4   ad = *(const int4*)(AD + (size_t)e * EE + f);
                float4 cc = *(const float4*)(MC + (size_t)e * EE + f);
                int   adr[4] = {ad.x, ad.y, ad.z, ad.w};
                float ccr[4] = {cc.x, cc.y, cc.z, cc.w};
                float sar[4] = {sa4.x, sa4.y, sa4.z, sa4.w};
                float outr[4];
#pragma unroll
                for (int j = 0; j < 4; j++) {
                    int jj = half * 4 + j;
                    float s  = (lane ? c[jj].y : c[jj].x) * inv_sq;
                    float sa = sar[j];
                    bool merge = (s > thr) && (sa != 0.0f);
                    float co = ccr[j];
                    float r = merge ? (1.0f - co) * s + co * sa : s;
                    if (adr[j] == 0) r = -FLT_MAX;
                    outr[j] = r;
                }
                float4 o = {outr[0], outr[1], outr[2], outr[3]};
                *(float4*)(S + (size_t)e * EE + f) = o;
            }
        }
    }
}

// ---------------------------------------------------------------------------
// Kernel 3: row softmax -> fp16 probs in g_s16
// ---------------------------------------------------------------------------
__global__ void __launch_bounds__(256) softmax_kernel()
{
    size_t row = blockIdx.x;
    float* S = g_s + row * EE;
    __half* S16 = g_s16 + row * EE;
    int tid = threadIdx.x;

    float v[8];
    float m = -FLT_MAX;
#pragma unroll
    for (int i = 0; i < 8; i++) {
        v[i] = S[tid + i * 256];
        m = fmaxf(m, v[i]);
    }
    __shared__ float redm[8];
    __shared__ float reds[8];
#pragma unroll
    for (int o = 16; o > 0; o >>= 1) m = fmaxf(m, __shfl_xor_sync(~0u, m, o));
    if ((tid & 31) == 0) redm[tid >> 5] = m;
    __syncthreads();
#pragma unroll
    for (int i = 0; i < 8; i++) m = fmaxf(m, redm[i]);

    float s = 0.f;
#pragma unroll
    for (int i = 0; i < 8; i++) {
        v[i] = __expf(v[i] - m);
        s += v[i];
    }
#pragma unroll
    for (int o = 16; o > 0; o >>= 1) s += __shfl_xor_sync(~0u, s, o);
    if ((tid & 31) == 0) reds[tid >> 5] = s;
    __syncthreads();
    s = 0.f;
#pragma unroll
    for (int i = 0; i < 8; i++) s += reds[i];

    float inv = 1.0f / s;
#pragma unroll
    for (int i = 0; i < 8; i++)
        S16[tid + i * 256] = __float2half_rn(v[i] * inv);
}

// ---------------------------------------------------------------------------
// Kernel 4: out = attn @ v via HMMA mma.sync m16n8k16 (fp16 in, fp32 acc).
// A = g_s16[m][k] K-major; B = g_vt16[n][k] K-major ('col' operand).
// CTA tile 128x128, 8 warps in 2(M)x4(N), warp tile 64x32, K-chunk 64.
// grid (DD/128=4, EE/128=16, BB=8), 256 threads.
// ---------------------------------------------------------------------------
__device__ __forceinline__ void ldm_x4(uint32_t* r, uint32_t addr) {
    asm volatile(
        "ldmatrix.sync.aligned.m8n8.x4.shared.b16 {%0,%1,%2,%3}, [%4];"
        : "=r"(r[0]), "=r"(r[1]), "=r"(r[2]), "=r"(r[3]) : "r"(addr));
}
__device__ __forceinline__ void mma16816(float* d, const uint32_t* a, const uint32_t* b) {
    asm volatile(
        "mma.sync.aligned.m16n8k16.row.col.f32.f16.f16.f32 "
        "{%0,%1,%2,%3}, {%4,%5,%6,%7}, {%8,%9}, {%0,%1,%2,%3};"
        : "+f"(d[0]), "+f"(d[1]), "+f"(d[2]), "+f"(d[3])
        : "r"(a[0]), "r"(a[1]), "r"(a[2]), "r"(a[3]), "r"(b[0]), "r"(b[1]));
}

__global__ void __launch_bounds__(256) av_hmma_kernel(float* __restrict__ out)
{
    __shared__ __align__(16) __half sA[128 * 64];
    __shared__ __align__(16) __half sB[128 * 64];

    const int tid = threadIdx.x;
    const int w = tid >> 5, lane = tid & 31;
    const int wm = w & 1, wn = w >> 1;       // 2 x 4 warp grid
    const int b = blockIdx.z;
    const int m0 = blockIdx.y * 128, n0 = blockIdx.x * 128;

    const __half* Ag = g_s16 + (size_t)b * EE * EE + (size_t)m0 * EE;
    const __half* Bg = g_vt16 + (size_t)b * DD * EE + (size_t)n0 * EE;
    float* C = out + (size_t)b * EE * DD;

    const uint32_t sA_a = smem_u32(sA), sB_a = smem_u32(sB);

    float acc[4][4][4];
#pragma unroll
    for (int mt = 0; mt < 4; mt++)
#pragma unroll
        for (int nt = 0; nt < 4; nt++)
#pragma unroll
            for (int q = 0; q < 4; q++) acc[mt][nt][q] = 0.f;

    // gmem->smem loader mapping: 128 rows x 8 16B-units
    const int lr = tid >> 1;            // row 0..127
    const int lu = (tid & 1) * 4;       // unit base (16B units) 0 or 4

    // ldmatrix lane address components
    const int a_m  = lane & 15;
    const int a_k8 = (lane >> 4) & 1;           // +8 halves in k
    const int b_n  = ((lane >> 4) & 1) * 8 + (lane & 7);
    const int b_k8 = (lane >> 3) & 1;

    for (int k0 = 0; k0 < EE; k0 += 64) {
#pragma unroll
        for (int i = 0; i < 4; i++) {
            int u = lu + i;
            uint32_t off = SW128B((uint32_t)(lr * 128 + u * 16));
            *(uint4*)((char*)sA + off) = *(const uint4*)(Ag + (size_t)lr * EE + k0 + u * 8);
            *(uint4*)((char*)sB + off) = *(const uint4*)(Bg + (size_t)lr * EE + k0 + u * 8);
        }
        __syncthreads();
#pragma unroll
        for (int ks = 0; ks < 4; ks++) {
            uint32_t afr[4][4];
#pragma unroll
            for (int mt = 0; mt < 4; mt++) {
                uint32_t off = SW128B((uint32_t)(
                    (wm * 64 + mt * 16 + a_m) * 128 + (ks * 16 + a_k8 * 8) * 2));
                ldm_x4(afr[mt], sA_a + off);
            }
            uint32_t bfr[4][2];
            {
                uint32_t off0 = SW128B((uint32_t)(
                    (wn * 32 + b_n) * 128 + (ks * 16 + b_k8 * 8) * 2));
                uint32_t r[4];
                ldm_x4(r, sB_a + off0);
                bfr[0][0] = r[0]; bfr[0][1] = r[1];
                bfr[1][0] = r[2]; bfr[1][1] = r[3];
                uint32_t off1 = SW128B((uint32_t)(
                    (wn * 32 + 16 + b_n) * 128 + (ks * 16 + b_k8 * 8) * 2));
                ldm_x4(r, sB_a + off1);
                bfr[2][0] = r[0]; bfr[2][1] = r[1];
                bfr[3][0] = r[2]; bfr[3][1] = r[3];
            }
#pragma unroll
            for (int mt = 0; mt < 4; mt++)
#pragma unroll
                for (int nt = 0; nt < 4; nt++)
                    mma16816(acc[mt][nt], afr[mt], bfr[nt]);
        }
        __syncthreads();
    }

    // epilogue: mma output frag: thread owns (m = lane/4 [+8], n = 2*(lane%4)+{0,1})
    const int eq = lane >> 2;
    const int er = (lane & 3) * 2;
#pragma unroll
    for (int mt = 0; mt < 4; mt++) {
#pragma unroll
        for (int nt = 0; nt < 4; nt++) {
            int m = m0 + wm * 64 + mt * 16 + eq;
            int n = n0 + wn * 32 + nt * 8 + er;
            float2 lo = {acc[mt][nt][0], acc[mt][nt][1]};
            float2 hi = {acc[mt][nt][2], acc[mt][nt][3]};
            *(float2*)(C + (size_t)m * DD + n) = lo;
            *(float2*)(C + (size_t)(m + 8) * DD + n) = hi;
        }
    }
}

// ---------------------------------------------------------------------------
extern "C" void kernel_launch(void* const* d_in, const int* in_sizes, int n_in,
                              void* d_out, int out_size)
{
    const float* x   = (const float*)d_in[0];
    const float* qa  = (const float*)d_in[1];
    const float* ka  = (const float*)d_in[2];
    const int*   adj = (const int*)  d_in[3];
    const float* mc  = (const float*)d_in[4];
    const float* Wq  = (const float*)d_in[5];
    const float* bq  = (const float*)d_in[6];
    const float* Wk  = (const float*)d_in[7];
    const float* bk  = (const float*)d_in[8];
    const float* Wv  = (const float*)d_in[9];
    const float* bv  = (const float*)d_in[10];
    const float* thr = (const float*)d_in[11];

    dim3 blk(256);
    proj_kernel<<<dim3(DD / 128, EE / 128, BB * 3), blk>>>(x, Wq, bq, Wk, bk, Wv, bv);
    vt_kernel<<<dim3(DD / 32, EE / 32, BB), 256>>>();
    scores_aux_kernel<<<dim3(EE / 128, EE / 128, BB), blk>>>(qa, ka);
    scores_main_kernel<<<dim3(EE / 128, EE / 128, BB), blk>>>(adj, mc, thr);
    softmax_kernel<<<BB * EE, 256>>>();
    av_hmma_kernel<<<dim3(DD / 128, EE / 128, BB), 256>>>((float*)d_out);
}